// round 15
// baseline (speedup 1.0000x reference)
#include <cuda_runtime.h>
#include <cuda_bf16.h>
#include <cuda_fp16.h>

#define N_NODES 50000
#define N_EDGES 800000
#define D 64
#define NBLK ((N_NODES + 255) / 256)   // 196

// ---------------------------------------------------------------------------
// Static device scratch. g_cnt zero at load; scatter_idx re-zeroes it each
// run (after scanfin has consumed it) -> graph-replay deterministic.
// ---------------------------------------------------------------------------
__device__ int    g_cnt[N_NODES];
__device__ int    g_offs[N_NODES + 1];
__device__ int    g_cursor[N_NODES];
__device__ int    g_sorted[N_EDGES];
__device__ float  g_Y[N_NODES * D];            // Y = feat @ W^T (fp32)
__device__ __half g_Yh[N_NODES * D];           // fp16 copy for gather traffic

// Side stream + events for graph-forked overlap (created at program init).
static cudaStream_t g_side;
static cudaEvent_t  g_evFork, g_evJoin;
namespace {
struct _Init {
    _Init() {
        cudaStreamCreateWithFlags(&g_side, cudaStreamNonBlocking);
        cudaEventCreateWithFlags(&g_evFork, cudaEventDisableTiming);
        cudaEventCreateWithFlags(&g_evJoin, cudaEventDisableTiming);
    }
} _g_init;
}

// ---------------------------------------------------------------------------
// 1) Histogram, 4 edges/thread (int4 loads, 4 independent REDs overlap)
// ---------------------------------------------------------------------------
__global__ __launch_bounds__(256) void hist_kernel(const int4* __restrict__ dst4,
                                                   int* __restrict__ cnt)
{
    int q = blockIdx.x * blockDim.x + threadIdx.x;
    if (q >= N_EDGES / 4) return;
    int4 d = __ldg(dst4 + q);
    atomicAdd(&cnt[d.x], 1);
    atomicAdd(&cnt[d.y], 1);
    atomicAdd(&cnt[d.z], 1);
    atomicAdd(&cnt[d.w], 1);
}

// ---------------------------------------------------------------------------
// 2) Merged scan: each block sums cnt[0..bid*256) for its base (L2-hot),
//    then scans its own 256 counters. scatter_idx re-zeroes cnt afterwards.
// ---------------------------------------------------------------------------
__global__ __launch_bounds__(256) void scanfin_kernel(
    const int* __restrict__ cnt, int* __restrict__ offs,
    int* __restrict__ cursor)
{
    __shared__ int sm[256];
    __shared__ int sbase[8];
    const int t = threadIdx.x;
    const int bid = blockIdx.x;

    const int4* cnt4 = (const int4*)cnt;
    int nq = bid * 64;
    int bv = 0;
    for (int i = t; i < nq; i += 256) {
        int4 v = __ldg(cnt4 + i);
        bv += (v.x + v.y) + (v.z + v.w);
    }
#pragma unroll
    for (int o = 16; o > 0; o >>= 1) bv += __shfl_down_sync(~0u, bv, o);
    if ((t & 31) == 0) sbase[t >> 5] = bv;

    int idx = bid * 256 + t;
    int c = (idx < N_NODES) ? __ldg(cnt + idx) : 0;
    sm[t] = c;
    __syncthreads();

    int base = sbase[0] + sbase[1] + sbase[2] + sbase[3] +
               sbase[4] + sbase[5] + sbase[6] + sbase[7];

    for (int off = 1; off < 256; off <<= 1) {
        int u = (t >= off) ? sm[t - off] : 0;
        __syncthreads();
        sm[t] += u;
        __syncthreads();
    }
    int off = base + sm[t] - c;   // exclusive prefix
    if (idx < N_NODES) {
        offs[idx]   = off;
        cursor[idx] = off;
        if (idx == N_NODES - 1) offs[N_NODES] = off + c;  // = N_EDGES
    }
}

// ---------------------------------------------------------------------------
// 3) Scatter, 4 edges/thread; also re-zeroes cnt for the next replay
// ---------------------------------------------------------------------------
__global__ __launch_bounds__(256) void scatter_idx_kernel(
    const int4* __restrict__ src4, const int4* __restrict__ dst4,
    int* __restrict__ cursor, int* __restrict__ sorted,
    int* __restrict__ cnt)
{
    int q = blockIdx.x * blockDim.x + threadIdx.x;
    if (q < N_NODES) cnt[q] = 0;              // replay reset (reads done)
    if (q >= N_EDGES / 4) return;
    int4 s = __ldg(src4 + q);
    int4 d = __ldg(dst4 + q);
    int p0 = atomicAdd(&cursor[d.x], 1);
    int p1 = atomicAdd(&cursor[d.y], 1);
    int p2 = atomicAdd(&cursor[d.z], 1);
    int p3 = atomicAdd(&cursor[d.w], 1);
    sorted[p0] = s.x;
    sorted[p1] = s.y;
    sorted[p2] = s.z;
    sorted[p3] = s.w;
}

// ---------------------------------------------------------------------------
// Helpers for the tf32 tensor-core GEMM
// ---------------------------------------------------------------------------
__device__ __forceinline__ unsigned f2tf32(float a) {
    unsigned r;
    asm("cvt.rna.tf32.f32 %0, %1;" : "=r"(r) : "f"(a));
    return r;
}
__device__ __forceinline__ void split_tf32(float a, unsigned& hi, unsigned& lo) {
    hi = f2tf32(a);
    lo = f2tf32(a - __uint_as_float(hi));
}
__device__ __forceinline__ void mma_tf32(float* c, unsigned a0, unsigned a1,
                                         unsigned a2, unsigned a3,
                                         unsigned b0, unsigned b1) {
    asm("mma.sync.aligned.m16n8k8.row.col.f32.tf32.tf32.f32 "
        "{%0,%1,%2,%3}, {%4,%5,%6,%7}, {%8,%9}, {%0,%1,%2,%3};"
        : "+f"(c[0]), "+f"(c[1]), "+f"(c[2]), "+f"(c[3])
        : "r"(a0), "r"(a1), "r"(a2), "r"(a3), "r"(b0), "r"(b1));
}

// ---------------------------------------------------------------------------
// 4) Y = feat @ W^T via mma.sync m16n8k8 tf32, 3xTF32 split (~fp32 acc).
//    R14 fragment semantics, with B splits HOISTED: W's tf32 hi/lo pairs
//    precomputed once per block into fragment-ordered smem
//    Bfrag[(jt*8+kt)*32 + lane] = {bh0, bl0, bh1, bl1}.
//    A tile in add-swizzled 64-float-stride layout:
//    col' = (col + 4*(row&7)) % 64 -> fragment banks (8kt+tg+4g)%32 all
//    distinct, float4 staging stays contiguous. Smem = 16K + 32K = 48K.
// ---------------------------------------------------------------------------
#define GR5 64   // rows per block

__global__ __launch_bounds__(128) void gemm_y_kernel(
    const float4* __restrict__ feat, const float4* __restrict__ W4,
    float* __restrict__ Y, __half2* __restrict__ Yh)
{
    __shared__ float tile[GR5 * 64];     // swizzled feat rows (16 KB)
    __shared__ uint4 Bfrag[8 * 8 * 32];  // pre-split W fragments (32 KB)

    const int tid  = threadIdx.x;
    const int row0 = blockIdx.x * GR5;
    const float* Wf = (const float*)W4;  // W[j][k], row-major 64x64

    // Stage feat tile with add-swizzle (float4-contiguous)
    for (int i = tid; i < GR5 * 16; i += 128) {
        int r = i >> 4, c4 = i & 15;
        int gr = row0 + r;
        float4 v = make_float4(0.f, 0.f, 0.f, 0.f);
        if (gr < N_NODES) v = feat[gr * 16 + c4];
        int c4s = (c4 + (r & 7)) & 15;   // swizzled float4 col
        ((float4*)tile)[r * 16 + c4s] = v;
    }
    // Precompute B fragments: 2048 entries, 16 per thread, 4 cvt each
    for (int i = tid; i < 8 * 8 * 32; i += 128) {
        int jt = i >> 8, kt = (i >> 5) & 7, ln = i & 31;
        int gg = ln >> 2, tg2 = ln & 3;
        int j = jt * 8 + gg;
        int k = kt * 8 + tg2;
        float f0 = __ldg(Wf + j * 64 + k);
        float f1 = __ldg(Wf + j * 64 + k + 4);
        unsigned bh0, bl0, bh1, bl1;
        split_tf32(f0, bh0, bl0);
        split_tf32(f1, bh1, bl1);
        Bfrag[i] = make_uint4(bh0, bl0, bh1, bl1);
    }
    __syncthreads();

    const int warp = tid >> 5;
    const int lane = tid & 31;
    const int g    = lane >> 2;      // 0..7
    const int tg   = lane & 3;       // 0..3
    const int r0   = warp * 16;      // warp's 16-row group

    float acc[8][4];
#pragma unroll
    for (int jt = 0; jt < 8; jt++)
#pragma unroll
        for (int q = 0; q < 4; q++) acc[jt][q] = 0.f;

    for (int kt = 0; kt < 8; kt++) {
        // A fragment (rows r0+g / r0+g+8, cols kt*8+tg / +4), swizzled cols
        int c0 = (kt * 8 + tg + 4 * g) & 63;
        int c1 = (kt * 8 + tg + 4 + 4 * g) & 63;
        float fa0 = tile[(r0 + g) * 64 + c0];
        float fa1 = tile[(r0 + g + 8) * 64 + c0];   // (g+8)&7 == g
        float fa2 = tile[(r0 + g) * 64 + c1];
        float fa3 = tile[(r0 + g + 8) * 64 + c1];
        unsigned ah0, al0, ah1, al1, ah2, al2, ah3, al3;
        split_tf32(fa0, ah0, al0);
        split_tf32(fa1, ah1, al1);
        split_tf32(fa2, ah2, al2);
        split_tf32(fa3, ah3, al3);

#pragma unroll
        for (int jt = 0; jt < 8; jt++) {
            uint4 bb = Bfrag[(jt * 8 + kt) * 32 + lane];
            // 3xTF32: hi*hi + hi*lo + lo*hi
            mma_tf32(acc[jt], ah0, ah1, ah2, ah3, bb.x, bb.z);
            mma_tf32(acc[jt], ah0, ah1, ah2, ah3, bb.y, bb.w);
            mma_tf32(acc[jt], al0, al1, al2, al3, bb.x, bb.z);
        }
    }

    // Epilogue: c0,c1 -> (row g, cols 2tg,2tg+1); c2,c3 -> row g+8
#pragma unroll
    for (int jt = 0; jt < 8; jt++) {
        int col = jt * 8 + 2 * tg;
        int rA = row0 + r0 + g;
        int rB = rA + 8;
        if (rA < N_NODES) {
            float2 v = make_float2(acc[jt][0], acc[jt][1]);
            *(float2*)(Y + rA * 64 + col) = v;
            Yh[(rA * 64 + col) >> 1] = __floats2half2_rn(v.x, v.y);
        }
        if (rB < N_NODES) {
            float2 v = make_float2(acc[jt][2], acc[jt][3]);
            *(float2*)(Y + rB * 64 + col) = v;
            Yh[(rB * 64 + col) >> 1] = __floats2half2_rn(v.x, v.y);
        }
    }
}

// ---------------------------------------------------------------------------
// 5) Final gather: out[g] = (1+eps)*Y[g] + sum_e Yh[src_e] + b
//    (proven: fp16 neighbor reads, fp32 accumulation + residual)
// ---------------------------------------------------------------------------
__global__ __launch_bounds__(256) void gather_final_kernel(
    const float4* __restrict__ Y, const uint2* __restrict__ Yh,
    const int* __restrict__ offs, const int* __restrict__ sorted,
    const float* __restrict__ eps, const float4* __restrict__ b4,
    float4* __restrict__ out)
{
    int g = (blockIdx.x * blockDim.x + threadIdx.x) >> 4;   // node
    int c = threadIdx.x & 15;
    if (g >= N_NODES) return;

    int beg = __ldg(offs + g);
    int end = __ldg(offs + g + 1);

    float4 a = make_float4(0.f, 0.f, 0.f, 0.f);
    int e = beg;
    for (; e + 4 <= end; e += 4) {
        int s0 = __ldg(sorted + e);
        int s1 = __ldg(sorted + e + 1);
        int s2 = __ldg(sorted + e + 2);
        int s3 = __ldg(sorted + e + 3);
        uint2 p0 = Yh[s0 * 16 + c];
        uint2 p1 = Yh[s1 * 16 + c];
        uint2 p2 = Yh[s2 * 16 + c];
        uint2 p3 = Yh[s3 * 16 + c];
        float2 f;
        f = __half22float2(*(__half2*)&p0.x); a.x += f.x; a.y += f.y;
        f = __half22float2(*(__half2*)&p0.y); a.z += f.x; a.w += f.y;
        f = __half22float2(*(__half2*)&p1.x); a.x += f.x; a.y += f.y;
        f = __half22float2(*(__half2*)&p1.y); a.z += f.x; a.w += f.y;
        f = __half22float2(*(__half2*)&p2.x); a.x += f.x; a.y += f.y;
        f = __half22float2(*(__half2*)&p2.y); a.z += f.x; a.w += f.y;
        f = __half22float2(*(__half2*)&p3.x); a.x += f.x; a.y += f.y;
        f = __half22float2(*(__half2*)&p3.y); a.z += f.x; a.w += f.y;
    }
    for (; e < end; e++) {
        int s = __ldg(sorted + e);
        uint2 p = Yh[s * 16 + c];
        float2 f;
        f = __half22float2(*(__half2*)&p.x); a.x += f.x; a.y += f.y;
        f = __half22float2(*(__half2*)&p.y); a.z += f.x; a.w += f.y;
    }

    float sc = 1.0f + __ldg(eps);
    float4 yg = Y[g * 16 + c];             // residual stays fp32
    float4 bb = __ldg(b4 + c);
    a.x += sc * yg.x + bb.x;
    a.y += sc * yg.y + bb.y;
    a.z += sc * yg.z + bb.z;
    a.w += sc * yg.w + bb.w;
    out[g * 16 + c] = a;
}

// ---------------------------------------------------------------------------
// Launch: inputs per metadata order: feat, W, b, eps, src, dst
// Fork: CSR build (side stream) overlaps GEMM (main stream).
// ---------------------------------------------------------------------------
extern "C" void kernel_launch(void* const* d_in, const int* in_sizes, int n_in,
                              void* d_out, int out_size)
{
    const float4* feat = (const float4*)d_in[0];
    const float4* W    = (const float4*)d_in[1];
    const float4* b4   = (const float4*)d_in[2];
    const float*  eps  = (const float*)d_in[3];
    const int4*   src4 = (const int4*)d_in[4];
    const int4*   dst4 = (const int4*)d_in[5];
    float4*       out  = (float4*)d_out;

    int *cnt, *offs, *cursor, *sorted;
    float* Y;
    __half* Yh;
    cudaGetSymbolAddress((void**)&cnt,    g_cnt);
    cudaGetSymbolAddress((void**)&offs,   g_offs);
    cudaGetSymbolAddress((void**)&cursor, g_cursor);
    cudaGetSymbolAddress((void**)&sorted, g_sorted);
    cudaGetSymbolAddress((void**)&Y,      g_Y);
    cudaGetSymbolAddress((void**)&Yh,     g_Yh);

    const int EQ = (N_EDGES / 4 + 255) / 256;   // 782 blocks, 4 edges/thread

    // Fork: CSR build chain on side stream
    cudaEventRecord(g_evFork, 0);
    cudaStreamWaitEvent(g_side, g_evFork, 0);
    hist_kernel<<<EQ, 256, 0, g_side>>>(dst4, cnt);
    scanfin_kernel<<<NBLK, 256, 0, g_side>>>(cnt, offs, cursor);
    scatter_idx_kernel<<<EQ, 256, 0, g_side>>>(src4, dst4, cursor, sorted, cnt);
    cudaEventRecord(g_evJoin, g_side);

    // Main stream: Y = feat @ W^T (tensor cores), overlaps the CSR build
    {
        int blocks = (N_NODES + GR5 - 1) / GR5;   // 782
        gemm_y_kernel<<<blocks, 128>>>(feat, W, Y, (__half2*)Yh);
    }

    // Join, then final gather writes out directly
    cudaStreamWaitEvent(0, g_evJoin, 0);
    {
        int threads = N_NODES * 16;
        gather_final_kernel<<<(threads + 255) / 256, 256>>>(
            (const float4*)Y, (const uint2*)Yh, offs, sorted, eps, b4, out);
    }
}

// round 16
// speedup vs baseline: 1.1104x; 1.1104x over previous
#include <cuda_runtime.h>
#include <cuda_bf16.h>
#include <cuda_fp16.h>

#define N_NODES 50000
#define N_EDGES 800000
#define D 64
#define NBLK ((N_NODES + 255) / 256)   // 196

// ---------------------------------------------------------------------------
// Static device scratch. g_cnt zero at load; scatter_idx re-zeroes it each
// run (after scanfin has consumed it) -> graph-replay deterministic.
// ---------------------------------------------------------------------------
__device__ int    g_cnt[N_NODES];
__device__ int    g_offs[N_NODES + 1];
__device__ int    g_cursor[N_NODES];
__device__ int    g_sorted[N_EDGES];
__device__ float  g_Y[N_NODES * D];            // Y = feat @ W^T (fp32)
__device__ __half g_Yh[N_NODES * D];           // fp16 copy for gather traffic

// Side stream + events for graph-forked overlap (created at program init).
static cudaStream_t g_side;
static cudaEvent_t  g_evFork, g_evJoin;
namespace {
struct _Init {
    _Init() {
        cudaStreamCreateWithFlags(&g_side, cudaStreamNonBlocking);
        cudaEventCreateWithFlags(&g_evFork, cudaEventDisableTiming);
        cudaEventCreateWithFlags(&g_evJoin, cudaEventDisableTiming);
    }
} _g_init;
}

// ---------------------------------------------------------------------------
// 1) Histogram, 4 edges/thread (int4 loads, 4 independent REDs overlap)
// ---------------------------------------------------------------------------
__global__ __launch_bounds__(256) void hist_kernel(const int4* __restrict__ dst4,
                                                   int* __restrict__ cnt)
{
    int q = blockIdx.x * blockDim.x + threadIdx.x;
    if (q >= N_EDGES / 4) return;
    int4 d = __ldg(dst4 + q);
    atomicAdd(&cnt[d.x], 1);
    atomicAdd(&cnt[d.y], 1);
    atomicAdd(&cnt[d.z], 1);
    atomicAdd(&cnt[d.w], 1);
}

// ---------------------------------------------------------------------------
// 2) Merged scan: each block sums cnt[0..bid*256) for its base (L2-hot),
//    then scans its own 256 counters. scatter_idx re-zeroes cnt afterwards.
// ---------------------------------------------------------------------------
__global__ __launch_bounds__(256) void scanfin_kernel(
    const int* __restrict__ cnt, int* __restrict__ offs,
    int* __restrict__ cursor)
{
    __shared__ int sm[256];
    __shared__ int sbase[8];
    const int t = threadIdx.x;
    const int bid = blockIdx.x;

    const int4* cnt4 = (const int4*)cnt;
    int nq = bid * 64;
    int bv = 0;
    for (int i = t; i < nq; i += 256) {
        int4 v = __ldg(cnt4 + i);
        bv += (v.x + v.y) + (v.z + v.w);
    }
#pragma unroll
    for (int o = 16; o > 0; o >>= 1) bv += __shfl_down_sync(~0u, bv, o);
    if ((t & 31) == 0) sbase[t >> 5] = bv;

    int idx = bid * 256 + t;
    int c = (idx < N_NODES) ? __ldg(cnt + idx) : 0;
    sm[t] = c;
    __syncthreads();

    int base = sbase[0] + sbase[1] + sbase[2] + sbase[3] +
               sbase[4] + sbase[5] + sbase[6] + sbase[7];

    for (int off = 1; off < 256; off <<= 1) {
        int u = (t >= off) ? sm[t - off] : 0;
        __syncthreads();
        sm[t] += u;
        __syncthreads();
    }
    int off = base + sm[t] - c;   // exclusive prefix
    if (idx < N_NODES) {
        offs[idx]   = off;
        cursor[idx] = off;
        if (idx == N_NODES - 1) offs[N_NODES] = off + c;  // = N_EDGES
    }
}

// ---------------------------------------------------------------------------
// 3) Scatter, 4 edges/thread; also re-zeroes cnt for the next replay
// ---------------------------------------------------------------------------
__global__ __launch_bounds__(256) void scatter_idx_kernel(
    const int4* __restrict__ src4, const int4* __restrict__ dst4,
    int* __restrict__ cursor, int* __restrict__ sorted,
    int* __restrict__ cnt)
{
    int q = blockIdx.x * blockDim.x + threadIdx.x;
    if (q < N_NODES) cnt[q] = 0;              // replay reset (reads done)
    if (q >= N_EDGES / 4) return;
    int4 s = __ldg(src4 + q);
    int4 d = __ldg(dst4 + q);
    int p0 = atomicAdd(&cursor[d.x], 1);
    int p1 = atomicAdd(&cursor[d.y], 1);
    int p2 = atomicAdd(&cursor[d.z], 1);
    int p3 = atomicAdd(&cursor[d.w], 1);
    sorted[p0] = s.x;
    sorted[p1] = s.y;
    sorted[p2] = s.z;
    sorted[p3] = s.w;
}

// ---------------------------------------------------------------------------
// Helpers for the tf32 tensor-core GEMM
// ---------------------------------------------------------------------------
__device__ __forceinline__ unsigned f2tf32(float a) {
    unsigned r;
    asm("cvt.rna.tf32.f32 %0, %1;" : "=r"(r) : "f"(a));
    return r;
}
__device__ __forceinline__ void mma_tf32(float* c, unsigned a0, unsigned a1,
                                         unsigned a2, unsigned a3,
                                         unsigned b0, unsigned b1) {
    asm("mma.sync.aligned.m16n8k8.row.col.f32.tf32.tf32.f32 "
        "{%0,%1,%2,%3}, {%4,%5,%6,%7}, {%8,%9}, {%0,%1,%2,%3};"
        : "+f"(c[0]), "+f"(c[1]), "+f"(c[2]), "+f"(c[3])
        : "r"(a0), "r"(a1), "r"(a2), "r"(a3), "r"(b0), "r"(b1));
}

// ---------------------------------------------------------------------------
// 4) Y = feat @ W^T via mma.sync m16n8k8, SINGLE-PASS TF32.
//    Error budget: tf32 input rounding ~2.4e-4 RMS + fp16 gather 2e-4
//    -> ~3.6e-4 combined, threshold 1e-3.
//    R14's proven A-tile (stride-68, conflict-free) + B-hi fragments
//    precomputed into 16 KB smem (uint2 per lane-entry). mma count /3,
//    in-loop cvt 320 -> 32. Smem ~33.8 KB (same occupancy as R14).
// ---------------------------------------------------------------------------
#define GR5 64   // rows per block

__global__ __launch_bounds__(128) void gemm_y_kernel(
    const float4* __restrict__ feat, const float4* __restrict__ W4,
    float* __restrict__ Y, __half2* __restrict__ Yh)
{
    __shared__ float tile[GR5 * 68];     // feat rows, stride 68 (17.4 KB)
    __shared__ uint2 Bfrag[8 * 8 * 32];  // W hi fragments (16 KB)

    const int tid  = threadIdx.x;
    const int row0 = blockIdx.x * GR5;
    const float* Wf = (const float*)W4;  // W[j][k], row-major 64x64

    // Stage feat tile (R14-proven layout)
    for (int i = tid; i < GR5 * 16; i += 128) {
        int r = i >> 4, c = i & 15;
        int gr = row0 + r;
        float4 v = make_float4(0.f, 0.f, 0.f, 0.f);
        if (gr < N_NODES) v = feat[gr * 16 + c];
        ((float4*)(tile + r * 68))[c] = v;
    }
    // Precompute B hi-fragments: 2048 entries, 16/thread, 2 cvt each
    for (int i = tid; i < 8 * 8 * 32; i += 128) {
        int jt = i >> 8, kt = (i >> 5) & 7, ln = i & 31;
        int gg = ln >> 2, tg2 = ln & 3;
        int j = jt * 8 + gg;
        int k = kt * 8 + tg2;
        float f0 = __ldg(Wf + j * 64 + k);
        float f1 = __ldg(Wf + j * 64 + k + 4);
        Bfrag[i] = make_uint2(f2tf32(f0), f2tf32(f1));
    }
    __syncthreads();

    const int warp = tid >> 5;
    const int lane = tid & 31;
    const int g    = lane >> 2;      // 0..7
    const int tg   = lane & 3;       // 0..3
    const int r0   = warp * 16;      // warp's 16-row group

    float acc[8][4];
#pragma unroll
    for (int jt = 0; jt < 8; jt++)
#pragma unroll
        for (int q = 0; q < 4; q++) acc[jt][q] = 0.f;

    for (int kt = 0; kt < 8; kt++) {
        // A fragment (rows r0+g / r0+g+8, cols kt*8+tg / +4) — R14-proven
        unsigned ah0 = f2tf32(tile[(r0 + g) * 68 + kt * 8 + tg]);
        unsigned ah1 = f2tf32(tile[(r0 + g + 8) * 68 + kt * 8 + tg]);
        unsigned ah2 = f2tf32(tile[(r0 + g) * 68 + kt * 8 + tg + 4]);
        unsigned ah3 = f2tf32(tile[(r0 + g + 8) * 68 + kt * 8 + tg + 4]);

#pragma unroll
        for (int jt = 0; jt < 8; jt++) {
            uint2 bb = Bfrag[(jt * 8 + kt) * 32 + lane];
            mma_tf32(acc[jt], ah0, ah1, ah2, ah3, bb.x, bb.y);
        }
    }

    // Epilogue: c0,c1 -> (row g, cols 2tg,2tg+1); c2,c3 -> row g+8
#pragma unroll
    for (int jt = 0; jt < 8; jt++) {
        int col = jt * 8 + 2 * tg;
        int rA = row0 + r0 + g;
        int rB = rA + 8;
        if (rA < N_NODES) {
            float2 v = make_float2(acc[jt][0], acc[jt][1]);
            *(float2*)(Y + rA * 64 + col) = v;
            Yh[(rA * 64 + col) >> 1] = __floats2half2_rn(v.x, v.y);
        }
        if (rB < N_NODES) {
            float2 v = make_float2(acc[jt][2], acc[jt][3]);
            *(float2*)(Y + rB * 64 + col) = v;
            Yh[(rB * 64 + col) >> 1] = __floats2half2_rn(v.x, v.y);
        }
    }
}

// ---------------------------------------------------------------------------
// 5) Final gather: out[g] = (1+eps)*Y[g] + sum_e Yh[src_e] + b
//    (proven: fp16 neighbor reads, fp32 accumulation + residual)
// ---------------------------------------------------------------------------
__global__ __launch_bounds__(256) void gather_final_kernel(
    const float4* __restrict__ Y, const uint2* __restrict__ Yh,
    const int* __restrict__ offs, const int* __restrict__ sorted,
    const float* __restrict__ eps, const float4* __restrict__ b4,
    float4* __restrict__ out)
{
    int g = (blockIdx.x * blockDim.x + threadIdx.x) >> 4;   // node
    int c = threadIdx.x & 15;
    if (g >= N_NODES) return;

    int beg = __ldg(offs + g);
    int end = __ldg(offs + g + 1);

    float4 a = make_float4(0.f, 0.f, 0.f, 0.f);
    int e = beg;
    for (; e + 4 <= end; e += 4) {
        int s0 = __ldg(sorted + e);
        int s1 = __ldg(sorted + e + 1);
        int s2 = __ldg(sorted + e + 2);
        int s3 = __ldg(sorted + e + 3);
        uint2 p0 = Yh[s0 * 16 + c];
        uint2 p1 = Yh[s1 * 16 + c];
        uint2 p2 = Yh[s2 * 16 + c];
        uint2 p3 = Yh[s3 * 16 + c];
        float2 f;
        f = __half22float2(*(__half2*)&p0.x); a.x += f.x; a.y += f.y;
        f = __half22float2(*(__half2*)&p0.y); a.z += f.x; a.w += f.y;
        f = __half22float2(*(__half2*)&p1.x); a.x += f.x; a.y += f.y;
        f = __half22float2(*(__half2*)&p1.y); a.z += f.x; a.w += f.y;
        f = __half22float2(*(__half2*)&p2.x); a.x += f.x; a.y += f.y;
        f = __half22float2(*(__half2*)&p2.y); a.z += f.x; a.w += f.y;
        f = __half22float2(*(__half2*)&p3.x); a.x += f.x; a.y += f.y;
        f = __half22float2(*(__half2*)&p3.y); a.z += f.x; a.w += f.y;
    }
    for (; e < end; e++) {
        int s = __ldg(sorted + e);
        uint2 p = Yh[s * 16 + c];
        float2 f;
        f = __half22float2(*(__half2*)&p.x); a.x += f.x; a.y += f.y;
        f = __half22float2(*(__half2*)&p.y); a.z += f.x; a.w += f.y;
    }

    float sc = 1.0f + __ldg(eps);
    float4 yg = Y[g * 16 + c];             // residual stays fp32
    float4 bb = __ldg(b4 + c);
    a.x += sc * yg.x + bb.x;
    a.y += sc * yg.y + bb.y;
    a.z += sc * yg.z + bb.z;
    a.w += sc * yg.w + bb.w;
    out[g * 16 + c] = a;
}

// ---------------------------------------------------------------------------
// Launch: inputs per metadata order: feat, W, b, eps, src, dst
// Fork: CSR build (side stream) overlaps GEMM (main stream).
// ---------------------------------------------------------------------------
extern "C" void kernel_launch(void* const* d_in, const int* in_sizes, int n_in,
                              void* d_out, int out_size)
{
    const float4* feat = (const float4*)d_in[0];
    const float4* W    = (const float4*)d_in[1];
    const float4* b4   = (const float4*)d_in[2];
    const float*  eps  = (const float*)d_in[3];
    const int4*   src4 = (const int4*)d_in[4];
    const int4*   dst4 = (const int4*)d_in[5];
    float4*       out  = (float4*)d_out;

    int *cnt, *offs, *cursor, *sorted;
    float* Y;
    __half* Yh;
    cudaGetSymbolAddress((void**)&cnt,    g_cnt);
    cudaGetSymbolAddress((void**)&offs,   g_offs);
    cudaGetSymbolAddress((void**)&cursor, g_cursor);
    cudaGetSymbolAddress((void**)&sorted, g_sorted);
    cudaGetSymbolAddress((void**)&Y,      g_Y);
    cudaGetSymbolAddress((void**)&Yh,     g_Yh);

    const int EQ = (N_EDGES / 4 + 255) / 256;   // 782 blocks, 4 edges/thread

    // Fork: CSR build chain on side stream
    cudaEventRecord(g_evFork, 0);
    cudaStreamWaitEvent(g_side, g_evFork, 0);
    hist_kernel<<<EQ, 256, 0, g_side>>>(dst4, cnt);
    scanfin_kernel<<<NBLK, 256, 0, g_side>>>(cnt, offs, cursor);
    scatter_idx_kernel<<<EQ, 256, 0, g_side>>>(src4, dst4, cursor, sorted, cnt);
    cudaEventRecord(g_evJoin, g_side);

    // Main stream: Y = feat @ W^T (tensor cores), overlaps the CSR build
    {
        int blocks = (N_NODES + GR5 - 1) / GR5;   // 782
        gemm_y_kernel<<<blocks, 128>>>(feat, W, Y, (__half2*)Yh);
    }

    // Join, then final gather writes out directly
    cudaStreamWaitEvent(0, g_evJoin, 0);
    {
        int threads = N_NODES * 16;
        gather_final_kernel<<<(threads + 255) / 256, 256>>>(
            (const float4*)Y, (const uint2*)Yh, offs, sorted, eps, b4, out);
    }
}